// round 7
// baseline (speedup 1.0000x reference)
#include <cuda_runtime.h>
#include <math.h>

#define NN 50000
#define EE 250000
#define NCHUNK 98   // ceil((NN+1)/512)

// ---------------- scratch (static device globals; no allocs allowed) -------
__device__ float g_lin[NN * 256];   // per-conv linear output h = A @ W
__device__ float g_h0[NN * 256];    // layer-0 accumulated output
__device__ float g_h1[NN * 256];    // layer-1 accumulated output
__device__ float g_ss[NN * 4];      // s_src per node/head
__device__ float g_sd[NN * 4];      // s_dst per node/head
__device__ float g_wpad[256 * 256]; // Wout padded 153 -> 256 cols
__device__ int   g_rpa[NN + 1];     // CSR row_ptr edge-type a
__device__ int   g_rpb[NN + 1];     // CSR row_ptr edge-type b
__device__ int   g_csa[EE];         // CSR src ids, dst-grouped, type a
__device__ int   g_csb[EE];         // type b
__device__ int   g_deg[NN + 1];
__device__ int   g_cur[NN];
__device__ int   g_part[128];

// ---------------- CSR build ------------------------------------------------
__global__ void zero_int_kernel(int* p, int n) {
    int i = blockIdx.x * blockDim.x + threadIdx.x;
    if (i < n) p[i] = 0;
}

__global__ void count_kernel(const int* __restrict__ dst, int* __restrict__ deg) {
    int e = blockIdx.x * blockDim.x + threadIdx.x;
    if (e < EE) atomicAdd(&deg[dst[e]], 1);
}

__global__ void scan_part_kernel(const int* __restrict__ deg, int* __restrict__ part) {
    __shared__ int s[512];
    int t = threadIdx.x;
    int i = blockIdx.x * 512 + t;
    s[t] = (i < NN + 1) ? deg[i] : 0;
    __syncthreads();
#pragma unroll
    for (int off = 256; off > 0; off >>= 1) {
        if (t < off) s[t] += s[t + off];
        __syncthreads();
    }
    if (t == 0) part[blockIdx.x] = s[0];
}

__global__ void scan_mid_kernel(int* part, int n) {
    if (threadIdx.x == 0 && blockIdx.x == 0) {
        int run = 0;
        for (int i = 0; i < n; i++) { int v = part[i]; part[i] = run; run += v; }
    }
}

__global__ void scan_final_kernel(const int* __restrict__ deg, const int* __restrict__ part,
                                  int* __restrict__ rowptr, int* __restrict__ cursor) {
    __shared__ int s[512];
    int t = threadIdx.x;
    int i = blockIdx.x * 512 + t;
    int v = (i < NN + 1) ? deg[i] : 0;
    s[t] = v;
    __syncthreads();
    for (int off = 1; off < 512; off <<= 1) {
        int x = (t >= off) ? s[t - off] : 0;
        __syncthreads();
        s[t] += x;
        __syncthreads();
    }
    int excl = s[t] - v + part[blockIdx.x];
    if (i < NN + 1) rowptr[i] = excl;
    if (i < NN) cursor[i] = excl;
}

__global__ void scatter_kernel(const int* __restrict__ src, const int* __restrict__ dst,
                               int* __restrict__ cursor, int* __restrict__ csrsrc) {
    int e = blockIdx.x * blockDim.x + threadIdx.x;
    if (e < EE) {
        int p = atomicAdd(&cursor[dst[e]], 1);
        csrsrc[p] = src[e];
    }
}

__global__ void pad_wout_kernel(const float* __restrict__ w, float* __restrict__ wp) {
    int i = blockIdx.x * blockDim.x + threadIdx.x;
    if (i < 256 * 256) {
        int r = i >> 8, c = i & 255;
        wp[i] = (c < 153) ? w[r * 153 + c] : 0.f;
    }
}

// ---------------- GEMM: C[M, NC] = A[M,256] @ B[256, NC(ld 256)] -----------
// BM=BN=128, BK=16, 256 threads, 8x8 per thread.
template <bool LRELU_A, bool HAS_BIAS, bool VEC_STORE>
__global__ void __launch_bounds__(256) gemm_kernel(
    const float* __restrict__ A, const float* __restrict__ B,
    const float* __restrict__ bias, float* __restrict__ C,
    int M, int NC, int ldC)
{
    __shared__ __align__(16) float As[16][132];
    __shared__ __align__(16) float Bs[16][128];
    const int tid = threadIdx.x;
    const int tx = tid & 15, ty = tid >> 4;
    const int m0 = blockIdx.x * 128, n0 = blockIdx.y * 128;

    float acc[8][8];
#pragma unroll
    for (int i = 0; i < 8; i++)
#pragma unroll
        for (int j = 0; j < 8; j++) acc[i][j] = 0.f;

    for (int kt = 0; kt < 256; kt += 16) {
#pragma unroll
        for (int r = 0; r < 2; r++) {
            int id = tid + r * 256;
            int row = id >> 2;
            int kq = (id & 3) << 2;
            float4 v = make_float4(0.f, 0.f, 0.f, 0.f);
            int gr = m0 + row;
            if (gr < M) v = *(const float4*)(A + (size_t)gr * 256 + kt + kq);
            if (LRELU_A) {
                v.x = v.x > 0.f ? v.x : 0.01f * v.x;
                v.y = v.y > 0.f ? v.y : 0.01f * v.y;
                v.z = v.z > 0.f ? v.z : 0.01f * v.z;
                v.w = v.w > 0.f ? v.w : 0.01f * v.w;
            }
            As[kq + 0][row] = v.x;
            As[kq + 1][row] = v.y;
            As[kq + 2][row] = v.z;
            As[kq + 3][row] = v.w;
        }
#pragma unroll
        for (int r = 0; r < 2; r++) {
            int id = tid + r * 256;
            int kr = id >> 5;
            int nq = (id & 31) << 2;
            float4 v = *(const float4*)(B + (size_t)(kt + kr) * 256 + n0 + nq);
            *(float4*)&Bs[kr][nq] = v;
        }
        __syncthreads();
#pragma unroll
        for (int kk = 0; kk < 16; kk++) {
            float a[8], b[8];
            *(float4*)(a)     = *(const float4*)&As[kk][ty * 8];
            *(float4*)(a + 4) = *(const float4*)&As[kk][ty * 8 + 4];
            *(float4*)(b)     = *(const float4*)&Bs[kk][tx * 8];
            *(float4*)(b + 4) = *(const float4*)&Bs[kk][tx * 8 + 4];
#pragma unroll
            for (int i = 0; i < 8; i++)
#pragma unroll
                for (int j = 0; j < 8; j++)
                    acc[i][j] = fmaf(a[i], b[j], acc[i][j]);
        }
        __syncthreads();
    }

#pragma unroll
    for (int i = 0; i < 8; i++) {
        int row = m0 + ty * 8 + i;
        if (row >= M) continue;
        if (VEC_STORE) {
            float4 v1 = make_float4(acc[i][0], acc[i][1], acc[i][2], acc[i][3]);
            float4 v2 = make_float4(acc[i][4], acc[i][5], acc[i][6], acc[i][7]);
            float* cp = C + (size_t)row * ldC + n0 + tx * 8;
            *(float4*)(cp) = v1;
            *(float4*)(cp + 4) = v2;
        } else {
#pragma unroll
            for (int j = 0; j < 8; j++) {
                int col = n0 + tx * 8 + j;
                if (col < NC) {
                    float v = acc[i][j];
                    if (HAS_BIAS) v += bias[col];
                    C[(size_t)row * ldC + col] = v;
                }
            }
        }
    }
}

// ---------------- per-node attention scores --------------------------------
// s_src[n,h] = sum_d h[n, h*64+d] * a_src[h,d];   warp per node.
__global__ void scores_kernel(const float* __restrict__ h,
                              const float* __restrict__ asrc,
                              const float* __restrict__ adst,
                              float* __restrict__ ss, float* __restrict__ sd)
{
    int w = threadIdx.x >> 5, lane = threadIdx.x & 31;
    int n = blockIdx.x * 8 + w;
    if (n >= NN) return;
    const float4* hp = (const float4*)(h + (size_t)n * 256);
    float4 v0 = hp[lane * 2], v1 = hp[lane * 2 + 1];
    const float4* ap = (const float4*)asrc;
    float4 a0 = ap[lane * 2], a1 = ap[lane * 2 + 1];
    const float4* bp = (const float4*)adst;
    float4 c0 = bp[lane * 2], c1 = bp[lane * 2 + 1];

    float ps = v0.x * a0.x + v0.y * a0.y + v0.z * a0.z + v0.w * a0.w +
               v1.x * a1.x + v1.y * a1.y + v1.z * a1.z + v1.w * a1.w;
    float pd = v0.x * c0.x + v0.y * c0.y + v0.z * c0.z + v0.w * c0.w +
               v1.x * c1.x + v1.y * c1.y + v1.z * c1.z + v1.w * c1.w;
#pragma unroll
    for (int off = 4; off > 0; off >>= 1) {
        ps += __shfl_xor_sync(0xffffffffu, ps, off);
        pd += __shfl_xor_sync(0xffffffffu, pd, off);
    }
    if ((lane & 7) == 0) {
        ss[n * 4 + (lane >> 3)] = ps;
        sd[n * 4 + (lane >> 3)] = pd;
    }
}

// ---------------- GAT aggregation: warp per dst node ------------------------
// out[dst] = (sum_e exp(lrelu(s_src[src]+s_dst[dst]) - max) * h[src]) / z + bias
__global__ void aggregate_kernel(const float* __restrict__ h,
                                 const int* __restrict__ rowptr,
                                 const int* __restrict__ csrsrc,
                                 const float* __restrict__ ss,
                                 const float* __restrict__ sd,
                                 const float* __restrict__ bias,
                                 float* __restrict__ out, int addFlag)
{
    __shared__ float sp[8][32][4];
    __shared__ int   sid[8][32];
    int w = threadIdx.x >> 5, lane = threadIdx.x & 31;
    int dst = blockIdx.x * 8 + w;
    if (dst >= NN) return;
    int beg = rowptr[dst], end = rowptr[dst + 1];

    float4 sdv = *(const float4*)(sd + dst * 4);

    // pass A: per-head max over edges (edge-parallel across lanes)
    float4 mx = make_float4(-1e30f, -1e30f, -1e30f, -1e30f);
    for (int i = beg + lane; i < end; i += 32) {
        int s = csrsrc[i];
        float4 sv = *(const float4*)(ss + s * 4);
        float e;
        e = sv.x + sdv.x; e = e > 0.f ? e : 0.2f * e; mx.x = fmaxf(mx.x, e);
        e = sv.y + sdv.y; e = e > 0.f ? e : 0.2f * e; mx.y = fmaxf(mx.y, e);
        e = sv.z + sdv.z; e = e > 0.f ? e : 0.2f * e; mx.z = fmaxf(mx.z, e);
        e = sv.w + sdv.w; e = e > 0.f ? e : 0.2f * e; mx.w = fmaxf(mx.w, e);
    }
#pragma unroll
    for (int off = 16; off > 0; off >>= 1) {
        mx.x = fmaxf(mx.x, __shfl_xor_sync(0xffffffffu, mx.x, off));
        mx.y = fmaxf(mx.y, __shfl_xor_sync(0xffffffffu, mx.y, off));
        mx.z = fmaxf(mx.z, __shfl_xor_sync(0xffffffffu, mx.z, off));
        mx.w = fmaxf(mx.w, __shfl_xor_sync(0xffffffffu, mx.w, off));
    }

    // pass B: chunked — compute p per (edge, head) into smem, accumulate
    // z and weighted feature sums. Lane owns feats [lane*4, lane*4+4) (head
    // lane>>4) and [128+lane*4, ...) (head 2+(lane>>4)).
    float acc[8];
#pragma unroll
    for (int i = 0; i < 8; i++) acc[i] = 0.f;
    float z0 = 0.f, z1 = 0.f, z2 = 0.f, z3 = 0.f;
    int hsel = lane >> 4;  // 0 or 1

    for (int c = beg; c < end; c += 32) {
        int cnt = min(32, end - c);
        if (lane < cnt) {
            int s = csrsrc[c + lane];
            sid[w][lane] = s;
            float4 sv = *(const float4*)(ss + s * 4);
            float e, p;
            e = sv.x + sdv.x; e = e > 0.f ? e : 0.2f * e; p = __expf(e - mx.x); sp[w][lane][0] = p; z0 += p;
            e = sv.y + sdv.y; e = e > 0.f ? e : 0.2f * e; p = __expf(e - mx.y); sp[w][lane][1] = p; z1 += p;
            e = sv.z + sdv.z; e = e > 0.f ? e : 0.2f * e; p = __expf(e - mx.z); sp[w][lane][2] = p; z2 += p;
            e = sv.w + sdv.w; e = e > 0.f ? e : 0.2f * e; p = __expf(e - mx.w); sp[w][lane][3] = p; z3 += p;
        }
        __syncwarp();
        for (int j = 0; j < cnt; j++) {
            int s = sid[w][j];
            float p1 = sp[w][j][hsel];
            float p2 = sp[w][j][hsel + 2];
            const float4* r = (const float4*)(h + (size_t)s * 256);
            float4 va = r[lane];
            float4 vb = r[32 + lane];
            acc[0] = fmaf(p1, va.x, acc[0]);
            acc[1] = fmaf(p1, va.y, acc[1]);
            acc[2] = fmaf(p1, va.z, acc[2]);
            acc[3] = fmaf(p1, va.w, acc[3]);
            acc[4] = fmaf(p2, vb.x, acc[4]);
            acc[5] = fmaf(p2, vb.y, acc[5]);
            acc[6] = fmaf(p2, vb.z, acc[6]);
            acc[7] = fmaf(p2, vb.w, acc[7]);
        }
        __syncwarp();
    }

#pragma unroll
    for (int off = 16; off > 0; off >>= 1) {
        z0 += __shfl_xor_sync(0xffffffffu, z0, off);
        z1 += __shfl_xor_sync(0xffffffffu, z1, off);
        z2 += __shfl_xor_sync(0xffffffffu, z2, off);
        z3 += __shfl_xor_sync(0xffffffffu, z3, off);
    }
    float i1 = 1.f / ((hsel ? z1 : z0) + 1e-16f);
    float i2 = 1.f / ((hsel ? z3 : z2) + 1e-16f);

    float* op = out + (size_t)dst * 256 + lane * 4;
    float4 bv1 = *(const float4*)(bias + lane * 4);
    float4 bv2 = *(const float4*)(bias + 128 + lane * 4);
    float4 r1 = make_float4(fmaf(acc[0], i1, bv1.x), fmaf(acc[1], i1, bv1.y),
                            fmaf(acc[2], i1, bv1.z), fmaf(acc[3], i1, bv1.w));
    float4 r2 = make_float4(fmaf(acc[4], i2, bv2.x), fmaf(acc[5], i2, bv2.y),
                            fmaf(acc[6], i2, bv2.z), fmaf(acc[7], i2, bv2.w));
    if (addFlag) {
        float4 o1 = *(const float4*)(op);
        float4 o2 = *(const float4*)(op + 128);
        r1.x += o1.x; r1.y += o1.y; r1.z += o1.z; r1.w += o1.w;
        r2.x += o2.x; r2.y += o2.y; r2.z += o2.z; r2.w += o2.w;
    }
    *(float4*)(op) = r1;
    *(float4*)(op + 128) = r2;
}

// ---------------- launcher --------------------------------------------------
extern "C" void kernel_launch(void* const* d_in, const int* in_sizes, int n_in,
                              void* d_out, int out_size)
{
    const float* x  = (const float*)d_in[0];
    const int*   ea = (const int*)d_in[1];
    const int*   eb = (const int*)d_in[2];
    // per-conv weights: W, a_src, a_dst, b
    const float* W0a = (const float*)d_in[3];
    const float* as0a = (const float*)d_in[4];
    const float* ad0a = (const float*)d_in[5];
    const float* b0a = (const float*)d_in[6];
    const float* W0b = (const float*)d_in[7];
    const float* as0b = (const float*)d_in[8];
    const float* ad0b = (const float*)d_in[9];
    const float* b0b = (const float*)d_in[10];
    const float* W1a = (const float*)d_in[11];
    const float* as1a = (const float*)d_in[12];
    const float* ad1a = (const float*)d_in[13];
    const float* b1a = (const float*)d_in[14];
    const float* W1b = (const float*)d_in[15];
    const float* as1b = (const float*)d_in[16];
    const float* ad1b = (const float*)d_in[17];
    const float* b1b = (const float*)d_in[18];
    const float* Wout = (const float*)d_in[19];
    const float* bout = (const float*)d_in[20];
    float* out = (float*)d_out;

    float *lin, *h0, *h1, *ssp, *sdp, *wpad;
    int *rpa, *rpb, *csa, *csb, *deg, *cur, *part;
    cudaGetSymbolAddress((void**)&lin, g_lin);
    cudaGetSymbolAddress((void**)&h0, g_h0);
    cudaGetSymbolAddress((void**)&h1, g_h1);
    cudaGetSymbolAddress((void**)&ssp, g_ss);
    cudaGetSymbolAddress((void**)&sdp, g_sd);
    cudaGetSymbolAddress((void**)&wpad, g_wpad);
    cudaGetSymbolAddress((void**)&rpa, g_rpa);
    cudaGetSymbolAddress((void**)&rpb, g_rpb);
    cudaGetSymbolAddress((void**)&csa, g_csa);
    cudaGetSymbolAddress((void**)&csb, g_csb);
    cudaGetSymbolAddress((void**)&deg, g_deg);
    cudaGetSymbolAddress((void**)&cur, g_cur);
    cudaGetSymbolAddress((void**)&part, g_part);

    const int* srca = ea;
    const int* dsta = ea + EE;
    const int* srcb = eb;
    const int* dstb = eb + EE;

    const int ZB = (NN + 1 + 255) / 256;
    const int EB = (EE + 255) / 256;

    // CSR for edge type a
    zero_int_kernel<<<ZB, 256>>>(deg, NN + 1);
    count_kernel<<<EB, 256>>>(dsta, deg);
    scan_part_kernel<<<NCHUNK, 512>>>(deg, part);
    scan_mid_kernel<<<1, 32>>>(part, NCHUNK);
    scan_final_kernel<<<NCHUNK, 512>>>(deg, part, rpa, cur);
    scatter_kernel<<<EB, 256>>>(srca, dsta, cur, csa);
    // CSR for edge type b
    zero_int_kernel<<<ZB, 256>>>(deg, NN + 1);
    count_kernel<<<EB, 256>>>(dstb, deg);
    scan_part_kernel<<<NCHUNK, 512>>>(deg, part);
    scan_mid_kernel<<<1, 32>>>(part, NCHUNK);
    scan_final_kernel<<<NCHUNK, 512>>>(deg, part, rpb, cur);
    scatter_kernel<<<EB, 256>>>(srcb, dstb, cur, csb);

    pad_wout_kernel<<<256, 256>>>(Wout, wpad);

    dim3 gemmGrid((NN + 127) / 128, 2);
    const int NODE_BLKS = (NN + 7) / 8;

    // layer 0, edge type a
    gemm_kernel<false, false, true><<<gemmGrid, 256>>>(x, W0a, nullptr, lin, NN, 256, 256);
    scores_kernel<<<NODE_BLKS, 256>>>(lin, as0a, ad0a, ssp, sdp);
    aggregate_kernel<<<NODE_BLKS, 256>>>(lin, rpa, csa, ssp, sdp, b0a, h0, 0);
    // layer 0, edge type b (adds into h0)
    gemm_kernel<false, false, true><<<gemmGrid, 256>>>(x, W0b, nullptr, lin, NN, 256, 256);
    scores_kernel<<<NODE_BLKS, 256>>>(lin, as0b, ad0b, ssp, sdp);
    aggregate_kernel<<<NODE_BLKS, 256>>>(lin, rpb, csb, ssp, sdp, b0b, h0, 1);
    // layer 1, edge type a (GEMM applies leaky_relu(0.01) to h0 on load)
    gemm_kernel<true, false, true><<<gemmGrid, 256>>>(h0, W1a, nullptr, lin, NN, 256, 256);
    scores_kernel<<<NODE_BLKS, 256>>>(lin, as1a, ad1a, ssp, sdp);
    aggregate_kernel<<<NODE_BLKS, 256>>>(lin, rpa, csa, ssp, sdp, b1a, h1, 0);
    // layer 1, edge type b
    gemm_kernel<true, false, true><<<gemmGrid, 256>>>(h0, W1b, nullptr, lin, NN, 256, 256);
    scores_kernel<<<NODE_BLKS, 256>>>(lin, as1b, ad1b, ssp, sdp);
    aggregate_kernel<<<NODE_BLKS, 256>>>(lin, rpb, csb, ssp, sdp, b1b, h1, 1);
    // output projection: out = h1 @ Wout + bout  (NC=153, ld 153, scalar store)
    gemm_kernel<false, true, false><<<gemmGrid, 256>>>(h1, wpad, bout, out, NN, 153, 153);
}

// round 8
// speedup vs baseline: 1.0002x; 1.0002x over previous
#include <cuda_runtime.h>
#include <math.h>

#define NN 50000
#define EE 250000
#define NCHUNK 98   // ceil((NN+1)/512)

// ---------------- scratch (static device globals; no allocs allowed) -------
__device__ float g_lin[NN * 256];   // per-conv linear output h = A @ W
__device__ float g_h0[NN * 256];    // layer-0 accumulated output
__device__ float g_h1[NN * 256];    // layer-1 accumulated output
__device__ float g_ss[NN * 4];      // s_src per node/head
__device__ float g_sd[NN * 4];      // s_dst per node/head
__device__ float g_wpad[256 * 256]; // Wout padded 153 -> 256 cols
__device__ int   g_rpa[NN + 1];     // CSR row_ptr edge-type a
__device__ int   g_rpb[NN + 1];     // CSR row_ptr edge-type b
__device__ int   g_csa[EE];         // CSR src ids, dst-grouped, type a
__device__ int   g_csb[EE];         // type b
__device__ int   g_deg[NN + 1];
__device__ int   g_cur[NN];
__device__ int   g_part[128];

// ---------------- CSR build ------------------------------------------------
__global__ void zero_int_kernel(int* p, int n) {
    int i = blockIdx.x * blockDim.x + threadIdx.x;
    if (i < n) p[i] = 0;
}

__global__ void count_kernel(const int* __restrict__ dst, int* __restrict__ deg) {
    int e = blockIdx.x * blockDim.x + threadIdx.x;
    if (e < EE) atomicAdd(&deg[dst[e]], 1);
}

__global__ void scan_part_kernel(const int* __restrict__ deg, int* __restrict__ part) {
    __shared__ int s[512];
    int t = threadIdx.x;
    int i = blockIdx.x * 512 + t;
    s[t] = (i < NN + 1) ? deg[i] : 0;
    __syncthreads();
#pragma unroll
    for (int off = 256; off > 0; off >>= 1) {
        if (t < off) s[t] += s[t + off];
        __syncthreads();
    }
    if (t == 0) part[blockIdx.x] = s[0];
}

__global__ void scan_mid_kernel(int* part, int n) {
    if (threadIdx.x == 0 && blockIdx.x == 0) {
        int run = 0;
        for (int i = 0; i < n; i++) { int v = part[i]; part[i] = run; run += v; }
    }
}

__global__ void scan_final_kernel(const int* __restrict__ deg, const int* __restrict__ part,
                                  int* __restrict__ rowptr, int* __restrict__ cursor) {
    __shared__ int s[512];
    int t = threadIdx.x;
    int i = blockIdx.x * 512 + t;
    int v = (i < NN + 1) ? deg[i] : 0;
    s[t] = v;
    __syncthreads();
    for (int off = 1; off < 512; off <<= 1) {
        int x = (t >= off) ? s[t - off] : 0;
        __syncthreads();
        s[t] += x;
        __syncthreads();
    }
    int excl = s[t] - v + part[blockIdx.x];
    if (i < NN + 1) rowptr[i] = excl;
    if (i < NN) cursor[i] = excl;
}

__global__ void scatter_kernel(const int* __restrict__ src, const int* __restrict__ dst,
                               int* __restrict__ cursor, int* __restrict__ csrsrc) {
    int e = blockIdx.x * blockDim.x + threadIdx.x;
    if (e < EE) {
        int p = atomicAdd(&cursor[dst[e]], 1);
        csrsrc[p] = src[e];
    }
}

__global__ void pad_wout_kernel(const float* __restrict__ w, float* __restrict__ wp) {
    int i = blockIdx.x * blockDim.x + threadIdx.x;
    if (i < 256 * 256) {
        int r = i >> 8, c = i & 255;
        wp[i] = (c < 153) ? w[r * 153 + c] : 0.f;
    }
}

// ---------------- GEMM: C[M, NC] = A[M,256] @ B[256, NC(ld 256)] -----------
// BM=BN=128, BK=16, 256 threads, 8x8 per thread.
template <bool LRELU_A, bool HAS_BIAS, bool VEC_STORE>
__global__ void __launch_bounds__(256) gemm_kernel(
    const float* __restrict__ A, const float* __restrict__ B,
    const float* __restrict__ bias, float* __restrict__ C,
    int M, int NC, int ldC)
{
    __shared__ __align__(16) float As[16][132];
    __shared__ __align__(16) float Bs[16][128];
    const int tid = threadIdx.x;
    const int tx = tid & 15, ty = tid >> 4;
    const int m0 = blockIdx.x * 128, n0 = blockIdx.y * 128;

    float acc[8][8];
#pragma unroll
    for (int i = 0; i < 8; i++)
#pragma unroll
        for (int j = 0; j < 8; j++) acc[i][j] = 0.f;

    for (int kt = 0; kt < 256; kt += 16) {
#pragma unroll
        for (int r = 0; r < 2; r++) {
            int id = tid + r * 256;
            int row = id >> 2;
            int kq = (id & 3) << 2;
            float4 v = make_float4(0.f, 0.f, 0.f, 0.f);
            int gr = m0 + row;
            if (gr < M) v = *(const float4*)(A + (size_t)gr * 256 + kt + kq);
            if (LRELU_A) {
                v.x = v.x > 0.f ? v.x : 0.01f * v.x;
                v.y = v.y > 0.f ? v.y : 0.01f * v.y;
                v.z = v.z > 0.f ? v.z : 0.01f * v.z;
                v.w = v.w > 0.f ? v.w : 0.01f * v.w;
            }
            As[kq + 0][row] = v.x;
            As[kq + 1][row] = v.y;
            As[kq + 2][row] = v.z;
            As[kq + 3][row] = v.w;
        }
#pragma unroll
        for (int r = 0; r < 2; r++) {
            int id = tid + r * 256;
            int kr = id >> 5;
            int nq = (id & 31) << 2;
            float4 v = *(const float4*)(B + (size_t)(kt + kr) * 256 + n0 + nq);
            *(float4*)&Bs[kr][nq] = v;
        }
        __syncthreads();
#pragma unroll
        for (int kk = 0; kk < 16; kk++) {
            float a[8], b[8];
            *(float4*)(a)     = *(const float4*)&As[kk][ty * 8];
            *(float4*)(a + 4) = *(const float4*)&As[kk][ty * 8 + 4];
            *(float4*)(b)     = *(const float4*)&Bs[kk][tx * 8];
            *(float4*)(b + 4) = *(const float4*)&Bs[kk][tx * 8 + 4];
#pragma unroll
            for (int i = 0; i < 8; i++)
#pragma unroll
                for (int j = 0; j < 8; j++)
                    acc[i][j] = fmaf(a[i], b[j], acc[i][j]);
        }
        __syncthreads();
    }

#pragma unroll
    for (int i = 0; i < 8; i++) {
        int row = m0 + ty * 8 + i;
        if (row >= M) continue;
        if (VEC_STORE) {
            float4 v1 = make_float4(acc[i][0], acc[i][1], acc[i][2], acc[i][3]);
            float4 v2 = make_float4(acc[i][4], acc[i][5], acc[i][6], acc[i][7]);
            float* cp = C + (size_t)row * ldC + n0 + tx * 8;
            *(float4*)(cp) = v1;
            *(float4*)(cp + 4) = v2;
        } else {
#pragma unroll
            for (int j = 0; j < 8; j++) {
                int col = n0 + tx * 8 + j;
                if (col < NC) {
                    float v = acc[i][j];
                    if (HAS_BIAS) v += bias[col];
                    C[(size_t)row * ldC + col] = v;
                }
            }
        }
    }
}

// ---------------- per-node attention scores --------------------------------
// s_src[n,h] = sum_d h[n, h*64+d] * a_src[h,d];   warp per node.
__global__ void scores_kernel(const float* __restrict__ h,
                              const float* __restrict__ asrc,
                              const float* __restrict__ adst,
                              float* __restrict__ ss, float* __restrict__ sd)
{
    int w = threadIdx.x >> 5, lane = threadIdx.x & 31;
    int n = blockIdx.x * 8 + w;
    if (n >= NN) return;
    const float4* hp = (const float4*)(h + (size_t)n * 256);
    float4 v0 = hp[lane * 2], v1 = hp[lane * 2 + 1];
    const float4* ap = (const float4*)asrc;
    float4 a0 = ap[lane * 2], a1 = ap[lane * 2 + 1];
    const float4* bp = (const float4*)adst;
    float4 c0 = bp[lane * 2], c1 = bp[lane * 2 + 1];

    float ps = v0.x * a0.x + v0.y * a0.y + v0.z * a0.z + v0.w * a0.w +
               v1.x * a1.x + v1.y * a1.y + v1.z * a1.z + v1.w * a1.w;
    float pd = v0.x * c0.x + v0.y * c0.y + v0.z * c0.z + v0.w * c0.w +
               v1.x * c1.x + v1.y * c1.y + v1.z * c1.z + v1.w * c1.w;
#pragma unroll
    for (int off = 4; off > 0; off >>= 1) {
        ps += __shfl_xor_sync(0xffffffffu, ps, off);
        pd += __shfl_xor_sync(0xffffffffu, pd, off);
    }
    if ((lane & 7) == 0) {
        ss[n * 4 + (lane >> 3)] = ps;
        sd[n * 4 + (lane >> 3)] = pd;
    }
}

// ---------------- GAT aggregation: warp per dst node ------------------------
// out[dst] = (sum_e exp(lrelu(s_src[src]+s_dst[dst]) - max) * h[src]) / z + bias
__global__ void aggregate_kernel(const float* __restrict__ h,
                                 const int* __restrict__ rowptr,
                                 const int* __restrict__ csrsrc,
                                 const float* __restrict__ ss,
                                 const float* __restrict__ sd,
                                 const float* __restrict__ bias,
                                 float* __restrict__ out, int addFlag)
{
    __shared__ float sp[8][32][4];
    __shared__ int   sid[8][32];
    int w = threadIdx.x >> 5, lane = threadIdx.x & 31;
    int dst = blockIdx.x * 8 + w;
    if (dst >= NN) return;
    int beg = rowptr[dst], end = rowptr[dst + 1];

    float4 sdv = *(const float4*)(sd + dst * 4);

    // pass A: per-head max over edges (edge-parallel across lanes)
    float4 mx = make_float4(-1e30f, -1e30f, -1e30f, -1e30f);
    for (int i = beg + lane; i < end; i += 32) {
        int s = csrsrc[i];
        float4 sv = *(const float4*)(ss + s * 4);
        float e;
        e = sv.x + sdv.x; e = e > 0.f ? e : 0.2f * e; mx.x = fmaxf(mx.x, e);
        e = sv.y + sdv.y; e = e > 0.f ? e : 0.2f * e; mx.y = fmaxf(mx.y, e);
        e = sv.z + sdv.z; e = e > 0.f ? e : 0.2f * e; mx.z = fmaxf(mx.z, e);
        e = sv.w + sdv.w; e = e > 0.f ? e : 0.2f * e; mx.w = fmaxf(mx.w, e);
    }
#pragma unroll
    for (int off = 16; off > 0; off >>= 1) {
        mx.x = fmaxf(mx.x, __shfl_xor_sync(0xffffffffu, mx.x, off));
        mx.y = fmaxf(mx.y, __shfl_xor_sync(0xffffffffu, mx.y, off));
        mx.z = fmaxf(mx.z, __shfl_xor_sync(0xffffffffu, mx.z, off));
        mx.w = fmaxf(mx.w, __shfl_xor_sync(0xffffffffu, mx.w, off));
    }

    // pass B: chunked — compute p per (edge, head) into smem, accumulate
    // z and weighted feature sums. Lane owns feats [lane*4, lane*4+4) (head
    // lane>>4) and [128+lane*4, ...) (head 2+(lane>>4)).
    float acc[8];
#pragma unroll
    for (int i = 0; i < 8; i++) acc[i] = 0.f;
    float z0 = 0.f, z1 = 0.f, z2 = 0.f, z3 = 0.f;
    int hsel = lane >> 4;  // 0 or 1

    for (int c = beg; c < end; c += 32) {
        int cnt = min(32, end - c);
        if (lane < cnt) {
            int s = csrsrc[c + lane];
            sid[w][lane] = s;
            float4 sv = *(const float4*)(ss + s * 4);
            float e, p;
            e = sv.x + sdv.x; e = e > 0.f ? e : 0.2f * e; p = __expf(e - mx.x); sp[w][lane][0] = p; z0 += p;
            e = sv.y + sdv.y; e = e > 0.f ? e : 0.2f * e; p = __expf(e - mx.y); sp[w][lane][1] = p; z1 += p;
            e = sv.z + sdv.z; e = e > 0.f ? e : 0.2f * e; p = __expf(e - mx.z); sp[w][lane][2] = p; z2 += p;
            e = sv.w + sdv.w; e = e > 0.f ? e : 0.2f * e; p = __expf(e - mx.w); sp[w][lane][3] = p; z3 += p;
        }
        __syncwarp();
        for (int j = 0; j < cnt; j++) {
            int s = sid[w][j];
            float p1 = sp[w][j][hsel];
            float p2 = sp[w][j][hsel + 2];
            const float4* r = (const float4*)(h + (size_t)s * 256);
            float4 va = r[lane];
            float4 vb = r[32 + lane];
            acc[0] = fmaf(p1, va.x, acc[0]);
            acc[1] = fmaf(p1, va.y, acc[1]);
            acc[2] = fmaf(p1, va.z, acc[2]);
            acc[3] = fmaf(p1, va.w, acc[3]);
            acc[4] = fmaf(p2, vb.x, acc[4]);
            acc[5] = fmaf(p2, vb.y, acc[5]);
            acc[6] = fmaf(p2, vb.z, acc[6]);
            acc[7] = fmaf(p2, vb.w, acc[7]);
        }
        __syncwarp();
    }

#pragma unroll
    for (int off = 16; off > 0; off >>= 1) {
        z0 += __shfl_xor_sync(0xffffffffu, z0, off);
        z1 += __shfl_xor_sync(0xffffffffu, z1, off);
        z2 += __shfl_xor_sync(0xffffffffu, z2, off);
        z3 += __shfl_xor_sync(0xffffffffu, z3, off);
    }
    float i1 = 1.f / ((hsel ? z1 : z0) + 1e-16f);
    float i2 = 1.f / ((hsel ? z3 : z2) + 1e-16f);

    float* op = out + (size_t)dst * 256 + lane * 4;
    float4 bv1 = *(const float4*)(bias + lane * 4);
    float4 bv2 = *(const float4*)(bias + 128 + lane * 4);
    float4 r1 = make_float4(fmaf(acc[0], i1, bv1.x), fmaf(acc[1], i1, bv1.y),
                            fmaf(acc[2], i1, bv1.z), fmaf(acc[3], i1, bv1.w));
    float4 r2 = make_float4(fmaf(acc[4], i2, bv2.x), fmaf(acc[5], i2, bv2.y),
                            fmaf(acc[6], i2, bv2.z), fmaf(acc[7], i2, bv2.w));
    if (addFlag) {
        float4 o1 = *(const float4*)(op);
        float4 o2 = *(const float4*)(op + 128);
        r1.x += o1.x; r1.y += o1.y; r1.z += o1.z; r1.w += o1.w;
        r2.x += o2.x; r2.y += o2.y; r2.z += o2.z; r2.w += o2.w;
    }
    *(float4*)(op) = r1;
    *(float4*)(op + 128) = r2;
}

// ---------------- launcher --------------------------------------------------
extern "C" void kernel_launch(void* const* d_in, const int* in_sizes, int n_in,
                              void* d_out, int out_size)
{
    const float* x  = (const float*)d_in[0];
    const int*   ea = (const int*)d_in[1];
    const int*   eb = (const int*)d_in[2];
    // per-conv weights: W, a_src, a_dst, b
    const float* W0a = (const float*)d_in[3];
    const float* as0a = (const float*)d_in[4];
    const float* ad0a = (const float*)d_in[5];
    const float* b0a = (const float*)d_in[6];
    const float* W0b = (const float*)d_in[7];
    const float* as0b = (const float*)d_in[8];
    const float* ad0b = (const float*)d_in[9];
    const float* b0b = (const float*)d_in[10];
    const float* W1a = (const float*)d_in[11];
    const float* as1a = (const float*)d_in[12];
    const float* ad1a = (const float*)d_in[13];
    const float* b1a = (const float*)d_in[14];
    const float* W1b = (const float*)d_in[15];
    const float* as1b = (const float*)d_in[16];
    const float* ad1b = (const float*)d_in[17];
    const float* b1b = (const float*)d_in[18];
    const float* Wout = (const float*)d_in[19];
    const float* bout = (const float*)d_in[20];
    float* out = (float*)d_out;

    float *lin, *h0, *h1, *ssp, *sdp, *wpad;
    int *rpa, *rpb, *csa, *csb, *deg, *cur, *part;
    cudaGetSymbolAddress((void**)&lin, g_lin);
    cudaGetSymbolAddress((void**)&h0, g_h0);
    cudaGetSymbolAddress((void**)&h1, g_h1);
    cudaGetSymbolAddress((void**)&ssp, g_ss);
    cudaGetSymbolAddress((void**)&sdp, g_sd);
    cudaGetSymbolAddress((void**)&wpad, g_wpad);
    cudaGetSymbolAddress((void**)&rpa, g_rpa);
    cudaGetSymbolAddress((void**)&rpb, g_rpb);
    cudaGetSymbolAddress((void**)&csa, g_csa);
    cudaGetSymbolAddress((void**)&csb, g_csb);
    cudaGetSymbolAddress((void**)&deg, g_deg);
    cudaGetSymbolAddress((void**)&cur, g_cur);
    cudaGetSymbolAddress((void**)&part, g_part);

    const int* srca = ea;
    const int* dsta = ea + EE;
    const int* srcb = eb;
    const int* dstb = eb + EE;

    const int ZB = (NN + 1 + 255) / 256;
    const int EB = (EE + 255) / 256;

    // CSR for edge type a
    zero_int_kernel<<<ZB, 256>>>(deg, NN + 1);
    count_kernel<<<EB, 256>>>(dsta, deg);
    scan_part_kernel<<<NCHUNK, 512>>>(deg, part);
    scan_mid_kernel<<<1, 32>>>(part, NCHUNK);
    scan_final_kernel<<<NCHUNK, 512>>>(deg, part, rpa, cur);
    scatter_kernel<<<EB, 256>>>(srca, dsta, cur, csa);
    // CSR for edge type b
    zero_int_kernel<<<ZB, 256>>>(deg, NN + 1);
    count_kernel<<<EB, 256>>>(dstb, deg);
    scan_part_kernel<<<NCHUNK, 512>>>(deg, part);
    scan_mid_kernel<<<1, 32>>>(part, NCHUNK);
    scan_final_kernel<<<NCHUNK, 512>>>(deg, part, rpb, cur);
    scatter_kernel<<<EB, 256>>>(srcb, dstb, cur, csb);

    pad_wout_kernel<<<256, 256>>>(Wout, wpad);

    dim3 gemmGrid((NN + 127) / 128, 2);
    const int NODE_BLKS = (NN + 7) / 8;

    // layer 0, edge type a
    gemm_kernel<false, false, true><<<gemmGrid, 256>>>(x, W0a, nullptr, lin, NN, 256, 256);
    scores_kernel<<<NODE_BLKS, 256>>>(lin, as0a, ad0a, ssp, sdp);
    aggregate_kernel<<<NODE_BLKS, 256>>>(lin, rpa, csa, ssp, sdp, b0a, h0, 0);
    // layer 0, edge type b (adds into h0)
    gemm_kernel<false, false, true><<<gemmGrid, 256>>>(x, W0b, nullptr, lin, NN, 256, 256);
    scores_kernel<<<NODE_BLKS, 256>>>(lin, as0b, ad0b, ssp, sdp);
    aggregate_kernel<<<NODE_BLKS, 256>>>(lin, rpb, csb, ssp, sdp, b0b, h0, 1);
    // layer 1, edge type a (GEMM applies leaky_relu(0.01) to h0 on load)
    gemm_kernel<true, false, true><<<gemmGrid, 256>>>(h0, W1a, nullptr, lin, NN, 256, 256);
    scores_kernel<<<NODE_BLKS, 256>>>(lin, as1a, ad1a, ssp, sdp);
    aggregate_kernel<<<NODE_BLKS, 256>>>(lin, rpa, csa, ssp, sdp, b1a, h1, 0);
    // layer 1, edge type b
    gemm_kernel<true, false, true><<<gemmGrid, 256>>>(h0, W1b, nullptr, lin, NN, 256, 256);
    scores_kernel<<<NODE_BLKS, 256>>>(lin, as1b, ad1b, ssp, sdp);
    aggregate_kernel<<<NODE_BLKS, 256>>>(lin, rpb, csb, ssp, sdp, b1b, h1, 1);
    // output projection: out = h1 @ Wout + bout  (NC=153, ld 153, scalar store)
    gemm_kernel<false, true, false><<<gemmGrid, 256>>>(h1, wpad, bout, out, NN, 153, 153);
}

// round 9
// speedup vs baseline: 1.0009x; 1.0008x over previous
#include <cuda_runtime.h>
#include <math.h>

#define NN 50000
#define EE 250000
#define NCHUNK 98   // ceil((NN+1)/512)

// ---------------- scratch (static device globals; no allocs allowed) -------
__device__ float g_lin[NN * 256];   // per-conv linear output h = A @ W
__device__ float g_h0[NN * 256];    // layer-0 accumulated output
__device__ float g_h1[NN * 256];    // layer-1 accumulated output
__device__ float g_ss[NN * 4];      // s_src per node/head
__device__ float g_sd[NN * 4];      // s_dst per node/head
__device__ float g_wpad[256 * 256]; // Wout padded 153 -> 256 cols
__device__ int   g_rpa[NN + 1];     // CSR row_ptr edge-type a
__device__ int   g_rpb[NN + 1];     // CSR row_ptr edge-type b
__device__ int   g_csa[EE];         // CSR src ids, dst-grouped, type a
__device__ int   g_csb[EE];         // type b
__device__ int   g_deg[NN + 1];
__device__ int   g_cur[NN];
__device__ int   g_part[128];

// ---------------- CSR build ------------------------------------------------
__global__ void zero_int_kernel(int* p, int n) {
    int i = blockIdx.x * blockDim.x + threadIdx.x;
    if (i < n) p[i] = 0;
}

__global__ void count_kernel(const int* __restrict__ dst, int* __restrict__ deg) {
    int e = blockIdx.x * blockDim.x + threadIdx.x;
    if (e < EE) atomicAdd(&deg[dst[e]], 1);
}

__global__ void scan_part_kernel(const int* __restrict__ deg, int* __restrict__ part) {
    __shared__ int s[512];
    int t = threadIdx.x;
    int i = blockIdx.x * 512 + t;
    s[t] = (i < NN + 1) ? deg[i] : 0;
    __syncthreads();
#pragma unroll
    for (int off = 256; off > 0; off >>= 1) {
        if (t < off) s[t] += s[t + off];
        __syncthreads();
    }
    if (t == 0) part[blockIdx.x] = s[0];
}

__global__ void scan_mid_kernel(int* part, int n) {
    if (threadIdx.x == 0 && blockIdx.x == 0) {
        int run = 0;
        for (int i = 0; i < n; i++) { int v = part[i]; part[i] = run; run += v; }
    }
}

__global__ void scan_final_kernel(const int* __restrict__ deg, const int* __restrict__ part,
                                  int* __restrict__ rowptr, int* __restrict__ cursor) {
    __shared__ int s[512];
    int t = threadIdx.x;
    int i = blockIdx.x * 512 + t;
    int v = (i < NN + 1) ? deg[i] : 0;
    s[t] = v;
    __syncthreads();
    for (int off = 1; off < 512; off <<= 1) {
        int x = (t >= off) ? s[t - off] : 0;
        __syncthreads();
        s[t] += x;
        __syncthreads();
    }
    int excl = s[t] - v + part[blockIdx.x];
    if (i < NN + 1) rowptr[i] = excl;
    if (i < NN) cursor[i] = excl;
}

__global__ void scatter_kernel(const int* __restrict__ src, const int* __restrict__ dst,
                               int* __restrict__ cursor, int* __restrict__ csrsrc) {
    int e = blockIdx.x * blockDim.x + threadIdx.x;
    if (e < EE) {
        int p = atomicAdd(&cursor[dst[e]], 1);
        csrsrc[p] = src[e];
    }
}

__global__ void pad_wout_kernel(const float* __restrict__ w, float* __restrict__ wp) {
    int i = blockIdx.x * blockDim.x + threadIdx.x;
    if (i < 256 * 256) {
        int r = i >> 8, c = i & 255;
        wp[i] = (c < 153) ? w[r * 153 + c] : 0.f;
    }
}

// ---------------- GEMM: C[M, NC] = A[M,256] @ B[256, NC(ld 256)] -----------
// BM=BN=128, BK=16, 256 threads, 8x8 per thread.
template <bool LRELU_A, bool HAS_BIAS, bool VEC_STORE>
__global__ void __launch_bounds__(256) gemm_kernel(
    const float* __restrict__ A, const float* __restrict__ B,
    const float* __restrict__ bias, float* __restrict__ C,
    int M, int NC, int ldC)
{
    __shared__ __align__(16) float As[16][132];
    __shared__ __align__(16) float Bs[16][128];
    const int tid = threadIdx.x;
    const int tx = tid & 15, ty = tid >> 4;
    const int m0 = blockIdx.x * 128, n0 = blockIdx.y * 128;

    float acc[8][8];
#pragma unroll
    for (int i = 0; i < 8; i++)
#pragma unroll
        for (int j = 0; j < 8; j++) acc[i][j] = 0.f;

    for (int kt = 0; kt < 256; kt += 16) {
#pragma unroll
        for (int r = 0; r < 2; r++) {
            int id = tid + r * 256;
            int row = id >> 2;
            int kq = (id & 3) << 2;
            float4 v = make_float4(0.f, 0.f, 0.f, 0.f);
            int gr = m0 + row;
            if (gr < M) v = *(const float4*)(A + (size_t)gr * 256 + kt + kq);
            if (LRELU_A) {
                v.x = v.x > 0.f ? v.x : 0.01f * v.x;
                v.y = v.y > 0.f ? v.y : 0.01f * v.y;
                v.z = v.z > 0.f ? v.z : 0.01f * v.z;
                v.w = v.w > 0.f ? v.w : 0.01f * v.w;
            }
            As[kq + 0][row] = v.x;
            As[kq + 1][row] = v.y;
            As[kq + 2][row] = v.z;
            As[kq + 3][row] = v.w;
        }
#pragma unroll
        for (int r = 0; r < 2; r++) {
            int id = tid + r * 256;
            int kr = id >> 5;
            int nq = (id & 31) << 2;
            float4 v = *(const float4*)(B + (size_t)(kt + kr) * 256 + n0 + nq);
            *(float4*)&Bs[kr][nq] = v;
        }
        __syncthreads();
#pragma unroll
        for (int kk = 0; kk < 16; kk++) {
            float a[8], b[8];
            *(float4*)(a)     = *(const float4*)&As[kk][ty * 8];
            *(float4*)(a + 4) = *(const float4*)&As[kk][ty * 8 + 4];
            *(float4*)(b)     = *(const float4*)&Bs[kk][tx * 8];
            *(float4*)(b + 4) = *(const float4*)&Bs[kk][tx * 8 + 4];
#pragma unroll
            for (int i = 0; i < 8; i++)
#pragma unroll
                for (int j = 0; j < 8; j++)
                    acc[i][j] = fmaf(a[i], b[j], acc[i][j]);
        }
        __syncthreads();
    }

#pragma unroll
    for (int i = 0; i < 8; i++) {
        int row = m0 + ty * 8 + i;
        if (row >= M) continue;
        if (VEC_STORE) {
            float4 v1 = make_float4(acc[i][0], acc[i][1], acc[i][2], acc[i][3]);
            float4 v2 = make_float4(acc[i][4], acc[i][5], acc[i][6], acc[i][7]);
            float* cp = C + (size_t)row * ldC + n0 + tx * 8;
            *(float4*)(cp) = v1;
            *(float4*)(cp + 4) = v2;
        } else {
#pragma unroll
            for (int j = 0; j < 8; j++) {
                int col = n0 + tx * 8 + j;
                if (col < NC) {
                    float v = acc[i][j];
                    if (HAS_BIAS) v += bias[col];
                    C[(size_t)row * ldC + col] = v;
                }
            }
        }
    }
}

// ---------------- per-node attention scores --------------------------------
// s_src[n,h] = sum_d h[n, h*64+d] * a_src[h,d];   warp per node.
__global__ void scores_kernel(const float* __restrict__ h,
                              const float* __restrict__ asrc,
                              const float* __restrict__ adst,
                              float* __restrict__ ss, float* __restrict__ sd)
{
    int w = threadIdx.x >> 5, lane = threadIdx.x & 31;
    int n = blockIdx.x * 8 + w;
    if (n >= NN) return;
    const float4* hp = (const float4*)(h + (size_t)n * 256);
    float4 v0 = hp[lane * 2], v1 = hp[lane * 2 + 1];
    const float4* ap = (const float4*)asrc;
    float4 a0 = ap[lane * 2], a1 = ap[lane * 2 + 1];
    const float4* bp = (const float4*)adst;
    float4 c0 = bp[lane * 2], c1 = bp[lane * 2 + 1];

    float ps = v0.x * a0.x + v0.y * a0.y + v0.z * a0.z + v0.w * a0.w +
               v1.x * a1.x + v1.y * a1.y + v1.z * a1.z + v1.w * a1.w;
    float pd = v0.x * c0.x + v0.y * c0.y + v0.z * c0.z + v0.w * c0.w +
               v1.x * c1.x + v1.y * c1.y + v1.z * c1.z + v1.w * c1.w;
#pragma unroll
    for (int off = 4; off > 0; off >>= 1) {
        ps += __shfl_xor_sync(0xffffffffu, ps, off);
        pd += __shfl_xor_sync(0xffffffffu, pd, off);
    }
    if ((lane & 7) == 0) {
        ss[n * 4 + (lane >> 3)] = ps;
        sd[n * 4 + (lane >> 3)] = pd;
    }
}

// ---------------- GAT aggregation: warp per dst node ------------------------
// out[dst] = (sum_e exp(lrelu(s_src[src]+s_dst[dst]) - max) * h[src]) / z + bias
__global__ void aggregate_kernel(const float* __restrict__ h,
                                 const int* __restrict__ rowptr,
                                 const int* __restrict__ csrsrc,
                                 const float* __restrict__ ss,
                                 const float* __restrict__ sd,
                                 const float* __restrict__ bias,
                                 float* __restrict__ out, int addFlag)
{
    __shared__ float sp[8][32][4];
    __shared__ int   sid[8][32];
    int w = threadIdx.x >> 5, lane = threadIdx.x & 31;
    int dst = blockIdx.x * 8 + w;
    if (dst >= NN) return;
    int beg = rowptr[dst], end = rowptr[dst + 1];

    float4 sdv = *(const float4*)(sd + dst * 4);

    // pass A: per-head max over edges (edge-parallel across lanes)
    float4 mx = make_float4(-1e30f, -1e30f, -1e30f, -1e30f);
    for (int i = beg + lane; i < end; i += 32) {
        int s = csrsrc[i];
        float4 sv = *(const float4*)(ss + s * 4);
        float e;
        e = sv.x + sdv.x; e = e > 0.f ? e : 0.2f * e; mx.x = fmaxf(mx.x, e);
        e = sv.y + sdv.y; e = e > 0.f ? e : 0.2f * e; mx.y = fmaxf(mx.y, e);
        e = sv.z + sdv.z; e = e > 0.f ? e : 0.2f * e; mx.z = fmaxf(mx.z, e);
        e = sv.w + sdv.w; e = e > 0.f ? e : 0.2f * e; mx.w = fmaxf(mx.w, e);
    }
#pragma unroll
    for (int off = 16; off > 0; off >>= 1) {
        mx.x = fmaxf(mx.x, __shfl_xor_sync(0xffffffffu, mx.x, off));
        mx.y = fmaxf(mx.y, __shfl_xor_sync(0xffffffffu, mx.y, off));
        mx.z = fmaxf(mx.z, __shfl_xor_sync(0xffffffffu, mx.z, off));
        mx.w = fmaxf(mx.w, __shfl_xor_sync(0xffffffffu, mx.w, off));
    }

    // pass B: chunked — compute p per (edge, head) into smem, accumulate
    // z and weighted feature sums. Lane owns feats [lane*4, lane*4+4) (head
    // lane>>4) and [128+lane*4, ...) (head 2+(lane>>4)).
    float acc[8];
#pragma unroll
    for (int i = 0; i < 8; i++) acc[i] = 0.f;
    float z0 = 0.f, z1 = 0.f, z2 = 0.f, z3 = 0.f;
    int hsel = lane >> 4;  // 0 or 1

    for (int c = beg; c < end; c += 32) {
        int cnt = min(32, end - c);
        if (lane < cnt) {
            int s = csrsrc[c + lane];
            sid[w][lane] = s;
            float4 sv = *(const float4*)(ss + s * 4);
            float e, p;
            e = sv.x + sdv.x; e = e > 0.f ? e : 0.2f * e; p = __expf(e - mx.x); sp[w][lane][0] = p; z0 += p;
            e = sv.y + sdv.y; e = e > 0.f ? e : 0.2f * e; p = __expf(e - mx.y); sp[w][lane][1] = p; z1 += p;
            e = sv.z + sdv.z; e = e > 0.f ? e : 0.2f * e; p = __expf(e - mx.z); sp[w][lane][2] = p; z2 += p;
            e = sv.w + sdv.w; e = e > 0.f ? e : 0.2f * e; p = __expf(e - mx.w); sp[w][lane][3] = p; z3 += p;
        }
        __syncwarp();
        for (int j = 0; j < cnt; j++) {
            int s = sid[w][j];
            float p1 = sp[w][j][hsel];
            float p2 = sp[w][j][hsel + 2];
            const float4* r = (const float4*)(h + (size_t)s * 256);
            float4 va = r[lane];
            float4 vb = r[32 + lane];
            acc[0] = fmaf(p1, va.x, acc[0]);
            acc[1] = fmaf(p1, va.y, acc[1]);
            acc[2] = fmaf(p1, va.z, acc[2]);
            acc[3] = fmaf(p1, va.w, acc[3]);
            acc[4] = fmaf(p2, vb.x, acc[4]);
            acc[5] = fmaf(p2, vb.y, acc[5]);
            acc[6] = fmaf(p2, vb.z, acc[6]);
            acc[7] = fmaf(p2, vb.w, acc[7]);
        }
        __syncwarp();
    }

#pragma unroll
    for (int off = 16; off > 0; off >>= 1) {
        z0 += __shfl_xor_sync(0xffffffffu, z0, off);
        z1 += __shfl_xor_sync(0xffffffffu, z1, off);
        z2 += __shfl_xor_sync(0xffffffffu, z2, off);
        z3 += __shfl_xor_sync(0xffffffffu, z3, off);
    }
    float i1 = 1.f / ((hsel ? z1 : z0) + 1e-16f);
    float i2 = 1.f / ((hsel ? z3 : z2) + 1e-16f);

    float* op = out + (size_t)dst * 256 + lane * 4;
    float4 bv1 = *(const float4*)(bias + lane * 4);
    float4 bv2 = *(const float4*)(bias + 128 + lane * 4);
    float4 r1 = make_float4(fmaf(acc[0], i1, bv1.x), fmaf(acc[1], i1, bv1.y),
                            fmaf(acc[2], i1, bv1.z), fmaf(acc[3], i1, bv1.w));
    float4 r2 = make_float4(fmaf(acc[4], i2, bv2.x), fmaf(acc[5], i2, bv2.y),
                            fmaf(acc[6], i2, bv2.z), fmaf(acc[7], i2, bv2.w));
    if (addFlag) {
        float4 o1 = *(const float4*)(op);
        float4 o2 = *(const float4*)(op + 128);
        r1.x += o1.x; r1.y += o1.y; r1.z += o1.z; r1.w += o1.w;
        r2.x += o2.x; r2.y += o2.y; r2.z += o2.z; r2.w += o2.w;
    }
    *(float4*)(op) = r1;
    *(float4*)(op + 128) = r2;
}

// ---------------- launcher --------------------------------------------------
extern "C" void kernel_launch(void* const* d_in, const int* in_sizes, int n_in,
                              void* d_out, int out_size)
{
    const float* x  = (const float*)d_in[0];
    const int*   ea = (const int*)d_in[1];
    const int*   eb = (const int*)d_in[2];
    // per-conv weights: W, a_src, a_dst, b
    const float* W0a = (const float*)d_in[3];
    const float* as0a = (const float*)d_in[4];
    const float* ad0a = (const float*)d_in[5];
    const float* b0a = (const float*)d_in[6];
    const float* W0b = (const float*)d_in[7];
    const float* as0b = (const float*)d_in[8];
    const float* ad0b = (const float*)d_in[9];
    const float* b0b = (const float*)d_in[10];
    const float* W1a = (const float*)d_in[11];
    const float* as1a = (const float*)d_in[12];
    const float* ad1a = (const float*)d_in[13];
    const float* b1a = (const float*)d_in[14];
    const float* W1b = (const float*)d_in[15];
    const float* as1b = (const float*)d_in[16];
    const float* ad1b = (const float*)d_in[17];
    const float* b1b = (const float*)d_in[18];
    const float* Wout = (const float*)d_in[19];
    const float* bout = (const float*)d_in[20];
    float* out = (float*)d_out;

    float *lin, *h0, *h1, *ssp, *sdp, *wpad;
    int *rpa, *rpb, *csa, *csb, *deg, *cur, *part;
    cudaGetSymbolAddress((void**)&lin, g_lin);
    cudaGetSymbolAddress((void**)&h0, g_h0);
    cudaGetSymbolAddress((void**)&h1, g_h1);
    cudaGetSymbolAddress((void**)&ssp, g_ss);
    cudaGetSymbolAddress((void**)&sdp, g_sd);
    cudaGetSymbolAddress((void**)&wpad, g_wpad);
    cudaGetSymbolAddress((void**)&rpa, g_rpa);
    cudaGetSymbolAddress((void**)&rpb, g_rpb);
    cudaGetSymbolAddress((void**)&csa, g_csa);
    cudaGetSymbolAddress((void**)&csb, g_csb);
    cudaGetSymbolAddress((void**)&deg, g_deg);
    cudaGetSymbolAddress((void**)&cur, g_cur);
    cudaGetSymbolAddress((void**)&part, g_part);

    const int* srca = ea;
    const int* dsta = ea + EE;
    const int* srcb = eb;
    const int* dstb = eb + EE;

    const int ZB = (NN + 1 + 255) / 256;
    const int EB = (EE + 255) / 256;

    // CSR for edge type a
    zero_int_kernel<<<ZB, 256>>>(deg, NN + 1);
    count_kernel<<<EB, 256>>>(dsta, deg);
    scan_part_kernel<<<NCHUNK, 512>>>(deg, part);
    scan_mid_kernel<<<1, 32>>>(part, NCHUNK);
    scan_final_kernel<<<NCHUNK, 512>>>(deg, part, rpa, cur);
    scatter_kernel<<<EB, 256>>>(srca, dsta, cur, csa);
    // CSR for edge type b
    zero_int_kernel<<<ZB, 256>>>(deg, NN + 1);
    count_kernel<<<EB, 256>>>(dstb, deg);
    scan_part_kernel<<<NCHUNK, 512>>>(deg, part);
    scan_mid_kernel<<<1, 32>>>(part, NCHUNK);
    scan_final_kernel<<<NCHUNK, 512>>>(deg, part, rpb, cur);
    scatter_kernel<<<EB, 256>>>(srcb, dstb, cur, csb);

    pad_wout_kernel<<<256, 256>>>(Wout, wpad);

    dim3 gemmGrid((NN + 127) / 128, 2);
    const int NODE_BLKS = (NN + 7) / 8;

    // layer 0, edge type a
    gemm_kernel<false, false, true><<<gemmGrid, 256>>>(x, W0a, nullptr, lin, NN, 256, 256);
    scores_kernel<<<NODE_BLKS, 256>>>(lin, as0a, ad0a, ssp, sdp);
    aggregate_kernel<<<NODE_BLKS, 256>>>(lin, rpa, csa, ssp, sdp, b0a, h0, 0);
    // layer 0, edge type b (adds into h0)
    gemm_kernel<false, false, true><<<gemmGrid, 256>>>(x, W0b, nullptr, lin, NN, 256, 256);
    scores_kernel<<<NODE_BLKS, 256>>>(lin, as0b, ad0b, ssp, sdp);
    aggregate_kernel<<<NODE_BLKS, 256>>>(lin, rpb, csb, ssp, sdp, b0b, h0, 1);
    // layer 1, edge type a (GEMM applies leaky_relu(0.01) to h0 on load)
    gemm_kernel<true, false, true><<<gemmGrid, 256>>>(h0, W1a, nullptr, lin, NN, 256, 256);
    scores_kernel<<<NODE_BLKS, 256>>>(lin, as1a, ad1a, ssp, sdp);
    aggregate_kernel<<<NODE_BLKS, 256>>>(lin, rpa, csa, ssp, sdp, b1a, h1, 0);
    // layer 1, edge type b
    gemm_kernel<true, false, true><<<gemmGrid, 256>>>(h0, W1b, nullptr, lin, NN, 256, 256);
    scores_kernel<<<NODE_BLKS, 256>>>(lin, as1b, ad1b, ssp, sdp);
    aggregate_kernel<<<NODE_BLKS, 256>>>(lin, rpb, csb, ssp, sdp, b1b, h1, 1);
    // output projection: out = h1 @ Wout + bout  (NC=153, ld 153, scalar store)
    gemm_kernel<false, true, false><<<gemmGrid, 256>>>(h1, wpad, bout, out, NN, 153, 153);
}

// round 10
// speedup vs baseline: 1.0049x; 1.0039x over previous
#include <cuda_runtime.h>
#include <math.h>

#define NN 50000
#define EE 250000
#define NCHUNK 98   // ceil((NN+1)/512)

// ---------------- scratch (static device globals; no allocs allowed) -------
__device__ float g_lin[NN * 256];   // per-conv linear output h = A @ W
__device__ float g_h0[NN * 256];    // layer-0 accumulated output
__device__ float g_h1[NN * 256];    // layer-1 accumulated output
__device__ float g_ss[NN * 4];      // s_src per node/head
__device__ float g_sd[NN * 4];      // s_dst per node/head
__device__ float g_wpad[256 * 256]; // Wout padded 153 -> 256 cols
__device__ int   g_rpa[NN + 1];     // CSR row_ptr edge-type a
__device__ int   g_rpb[NN + 1];     // CSR row_ptr edge-type b
__device__ int   g_csa[EE];         // CSR src ids, dst-grouped, type a
__device__ int   g_csb[EE];         // type b
__device__ int   g_deg[NN + 1];
__device__ int   g_cur[NN];
__device__ int   g_part[128];

// ---------------- CSR build ------------------------------------------------
__global__ void zero_int_kernel(int* p, int n) {
    int i = blockIdx.x * blockDim.x + threadIdx.x;
    if (i < n) p[i] = 0;
}

__global__ void count_kernel(const int* __restrict__ dst, int* __restrict__ deg) {
    int e = blockIdx.x * blockDim.x + threadIdx.x;
    if (e < EE) atomicAdd(&deg[dst[e]], 1);
}

__global__ void scan_part_kernel(const int* __restrict__ deg, int* __restrict__ part) {
    __shared__ int s[512];
    int t = threadIdx.x;
    int i = blockIdx.x * 512 + t;
    s[t] = (i < NN + 1) ? deg[i] : 0;
    __syncthreads();
#pragma unroll
    for (int off = 256; off > 0; off >>= 1) {
        if (t < off) s[t] += s[t + off];
        __syncthreads();
    }
    if (t == 0) part[blockIdx.x] = s[0];
}

__global__ void scan_mid_kernel(int* part, int n) {
    if (threadIdx.x == 0 && blockIdx.x == 0) {
        int run = 0;
        for (int i = 0; i < n; i++) { int v = part[i]; part[i] = run; run += v; }
    }
}

__global__ void scan_final_kernel(const int* __restrict__ deg, const int* __restrict__ part,
                                  int* __restrict__ rowptr, int* __restrict__ cursor) {
    __shared__ int s[512];
    int t = threadIdx.x;
    int i = blockIdx.x * 512 + t;
    int v = (i < NN + 1) ? deg[i] : 0;
    s[t] = v;
    __syncthreads();
    for (int off = 1; off < 512; off <<= 1) {
        int x = (t >= off) ? s[t - off] : 0;
        __syncthreads();
        s[t] += x;
        __syncthreads();
    }
    int excl = s[t] - v + part[blockIdx.x];
    if (i < NN + 1) rowptr[i] = excl;
    if (i < NN) cursor[i] = excl;
}

__global__ void scatter_kernel(const int* __restrict__ src, const int* __restrict__ dst,
                               int* __restrict__ cursor, int* __restrict__ csrsrc) {
    int e = blockIdx.x * blockDim.x + threadIdx.x;
    if (e < EE) {
        int p = atomicAdd(&cursor[dst[e]], 1);
        csrsrc[p] = src[e];
    }
}

__global__ void pad_wout_kernel(const float* __restrict__ w, float* __restrict__ wp) {
    int i = blockIdx.x * blockDim.x + threadIdx.x;
    if (i < 256 * 256) {
        int r = i >> 8, c = i & 255;
        wp[i] = (c < 153) ? w[r * 153 + c] : 0.f;
    }
}

// ---------------- GEMM: C[M, NC] = A[M,256] @ B[256, NC(ld 256)] -----------
// BM=BN=128, BK=16, 256 threads, 8x8 per thread.
template <bool LRELU_A, bool HAS_BIAS, bool VEC_STORE>
__global__ void __launch_bounds__(256) gemm_kernel(
    const float* __restrict__ A, const float* __restrict__ B,
    const float* __restrict__ bias, float* __restrict__ C,
    int M, int NC, int ldC)
{
    __shared__ __align__(16) float As[16][132];
    __shared__ __align__(16) float Bs[16][128];
    const int tid = threadIdx.x;
    const int tx = tid & 15, ty = tid >> 4;
    const int m0 = blockIdx.x * 128, n0 = blockIdx.y * 128;

    float acc[8][8];
#pragma unroll
    for (int i = 0; i < 8; i++)
#pragma unroll
        for (int j = 0; j < 8; j++) acc[i][j] = 0.f;

    for (int kt = 0; kt < 256; kt += 16) {
#pragma unroll
        for (int r = 0; r < 2; r++) {
            int id = tid + r * 256;
            int row = id >> 2;
            int kq = (id & 3) << 2;
            float4 v = make_float4(0.f, 0.f, 0.f, 0.f);
            int gr = m0 + row;
            if (gr < M) v = *(const float4*)(A + (size_t)gr * 256 + kt + kq);
            if (LRELU_A) {
                v.x = v.x > 0.f ? v.x : 0.01f * v.x;
                v.y = v.y > 0.f ? v.y : 0.01f * v.y;
                v.z = v.z > 0.f ? v.z : 0.01f * v.z;
                v.w = v.w > 0.f ? v.w : 0.01f * v.w;
            }
            As[kq + 0][row] = v.x;
            As[kq + 1][row] = v.y;
            As[kq + 2][row] = v.z;
            As[kq + 3][row] = v.w;
        }
#pragma unroll
        for (int r = 0; r < 2; r++) {
            int id = tid + r * 256;
            int kr = id >> 5;
            int nq = (id & 31) << 2;
            float4 v = *(const float4*)(B + (size_t)(kt + kr) * 256 + n0 + nq);
            *(float4*)&Bs[kr][nq] = v;
        }
        __syncthreads();
#pragma unroll
        for (int kk = 0; kk < 16; kk++) {
            float a[8], b[8];
            *(float4*)(a)     = *(const float4*)&As[kk][ty * 8];
            *(float4*)(a + 4) = *(const float4*)&As[kk][ty * 8 + 4];
            *(float4*)(b)     = *(const float4*)&Bs[kk][tx * 8];
            *(float4*)(b + 4) = *(const float4*)&Bs[kk][tx * 8 + 4];
#pragma unroll
            for (int i = 0; i < 8; i++)
#pragma unroll
                for (int j = 0; j < 8; j++)
                    acc[i][j] = fmaf(a[i], b[j], acc[i][j]);
        }
        __syncthreads();
    }

#pragma unroll
    for (int i = 0; i < 8; i++) {
        int row = m0 + ty * 8 + i;
        if (row >= M) continue;
        if (VEC_STORE) {
            float4 v1 = make_float4(acc[i][0], acc[i][1], acc[i][2], acc[i][3]);
            float4 v2 = make_float4(acc[i][4], acc[i][5], acc[i][6], acc[i][7]);
            float* cp = C + (size_t)row * ldC + n0 + tx * 8;
            *(float4*)(cp) = v1;
            *(float4*)(cp + 4) = v2;
        } else {
#pragma unroll
            for (int j = 0; j < 8; j++) {
                int col = n0 + tx * 8 + j;
                if (col < NC) {
                    float v = acc[i][j];
                    if (HAS_BIAS) v += bias[col];
                    C[(size_t)row * ldC + col] = v;
                }
            }
        }
    }
}

// ---------------- per-node attention scores --------------------------------
// s_src[n,h] = sum_d h[n, h*64+d] * a_src[h,d];   warp per node.
__global__ void scores_kernel(const float* __restrict__ h,
                              const float* __restrict__ asrc,
                              const float* __restrict__ adst,
                              float* __restrict__ ss, float* __restrict__ sd)
{
    int w = threadIdx.x >> 5, lane = threadIdx.x & 31;
    int n = blockIdx.x * 8 + w;
    if (n >= NN) return;
    const float4* hp = (const float4*)(h + (size_t)n * 256);
    float4 v0 = hp[lane * 2], v1 = hp[lane * 2 + 1];
    const float4* ap = (const float4*)asrc;
    float4 a0 = ap[lane * 2], a1 = ap[lane * 2 + 1];
    const float4* bp = (const float4*)adst;
    float4 c0 = bp[lane * 2], c1 = bp[lane * 2 + 1];

    float ps = v0.x * a0.x + v0.y * a0.y + v0.z * a0.z + v0.w * a0.w +
               v1.x * a1.x + v1.y * a1.y + v1.z * a1.z + v1.w * a1.w;
    float pd = v0.x * c0.x + v0.y * c0.y + v0.z * c0.z + v0.w * c0.w +
               v1.x * c1.x + v1.y * c1.y + v1.z * c1.z + v1.w * c1.w;
#pragma unroll
    for (int off = 4; off > 0; off >>= 1) {
        ps += __shfl_xor_sync(0xffffffffu, ps, off);
        pd += __shfl_xor_sync(0xffffffffu, pd, off);
    }
    if ((lane & 7) == 0) {
        ss[n * 4 + (lane >> 3)] = ps;
        sd[n * 4 + (lane >> 3)] = pd;
    }
}

// ---------------- GAT aggregation: warp per dst node ------------------------
// out[dst] = (sum_e exp(lrelu(s_src[src]+s_dst[dst]) - max) * h[src]) / z + bias
__global__ void aggregate_kernel(const float* __restrict__ h,
                                 const int* __restrict__ rowptr,
                                 const int* __restrict__ csrsrc,
                                 const float* __restrict__ ss,
                                 const float* __restrict__ sd,
                                 const float* __restrict__ bias,
                                 float* __restrict__ out, int addFlag)
{
    __shared__ float sp[8][32][4];
    __shared__ int   sid[8][32];
    int w = threadIdx.x >> 5, lane = threadIdx.x & 31;
    int dst = blockIdx.x * 8 + w;
    if (dst >= NN) return;
    int beg = rowptr[dst], end = rowptr[dst + 1];

    float4 sdv = *(const float4*)(sd + dst * 4);

    // pass A: per-head max over edges (edge-parallel across lanes)
    float4 mx = make_float4(-1e30f, -1e30f, -1e30f, -1e30f);
    for (int i = beg + lane; i < end; i += 32) {
        int s = csrsrc[i];
        float4 sv = *(const float4*)(ss + s * 4);
        float e;
        e = sv.x + sdv.x; e = e > 0.f ? e : 0.2f * e; mx.x = fmaxf(mx.x, e);
        e = sv.y + sdv.y; e = e > 0.f ? e : 0.2f * e; mx.y = fmaxf(mx.y, e);
        e = sv.z + sdv.z; e = e > 0.f ? e : 0.2f * e; mx.z = fmaxf(mx.z, e);
        e = sv.w + sdv.w; e = e > 0.f ? e : 0.2f * e; mx.w = fmaxf(mx.w, e);
    }
#pragma unroll
    for (int off = 16; off > 0; off >>= 1) {
        mx.x = fmaxf(mx.x, __shfl_xor_sync(0xffffffffu, mx.x, off));
        mx.y = fmaxf(mx.y, __shfl_xor_sync(0xffffffffu, mx.y, off));
        mx.z = fmaxf(mx.z, __shfl_xor_sync(0xffffffffu, mx.z, off));
        mx.w = fmaxf(mx.w, __shfl_xor_sync(0xffffffffu, mx.w, off));
    }

    // pass B: chunked — compute p per (edge, head) into smem, accumulate
    // z and weighted feature sums. Lane owns feats [lane*4, lane*4+4) (head
    // lane>>4) and [128+lane*4, ...) (head 2+(lane>>4)).
    float acc[8];
#pragma unroll
    for (int i = 0; i < 8; i++) acc[i] = 0.f;
    float z0 = 0.f, z1 = 0.f, z2 = 0.f, z3 = 0.f;
    int hsel = lane >> 4;  // 0 or 1

    for (int c = beg; c < end; c += 32) {
        int cnt = min(32, end - c);
        if (lane < cnt) {
            int s = csrsrc[c + lane];
            sid[w][lane] = s;
            float4 sv = *(const float4*)(ss + s * 4);
            float e, p;
            e = sv.x + sdv.x; e = e > 0.f ? e : 0.2f * e; p = __expf(e - mx.x); sp[w][lane][0] = p; z0 += p;
            e = sv.y + sdv.y; e = e > 0.f ? e : 0.2f * e; p = __expf(e - mx.y); sp[w][lane][1] = p; z1 += p;
            e = sv.z + sdv.z; e = e > 0.f ? e : 0.2f * e; p = __expf(e - mx.z); sp[w][lane][2] = p; z2 += p;
            e = sv.w + sdv.w; e = e > 0.f ? e : 0.2f * e; p = __expf(e - mx.w); sp[w][lane][3] = p; z3 += p;
        }
        __syncwarp();
        for (int j = 0; j < cnt; j++) {
            int s = sid[w][j];
            float p1 = sp[w][j][hsel];
            float p2 = sp[w][j][hsel + 2];
            const float4* r = (const float4*)(h + (size_t)s * 256);
            float4 va = r[lane];
            float4 vb = r[32 + lane];
            acc[0] = fmaf(p1, va.x, acc[0]);
            acc[1] = fmaf(p1, va.y, acc[1]);
            acc[2] = fmaf(p1, va.z, acc[2]);
            acc[3] = fmaf(p1, va.w, acc[3]);
            acc[4] = fmaf(p2, vb.x, acc[4]);
            acc[5] = fmaf(p2, vb.y, acc[5]);
            acc[6] = fmaf(p2, vb.z, acc[6]);
            acc[7] = fmaf(p2, vb.w, acc[7]);
        }
        __syncwarp();
    }

#pragma unroll
    for (int off = 16; off > 0; off >>= 1) {
        z0 += __shfl_xor_sync(0xffffffffu, z0, off);
        z1 += __shfl_xor_sync(0xffffffffu, z1, off);
        z2 += __shfl_xor_sync(0xffffffffu, z2, off);
        z3 += __shfl_xor_sync(0xffffffffu, z3, off);
    }
    float i1 = 1.f / ((hsel ? z1 : z0) + 1e-16f);
    float i2 = 1.f / ((hsel ? z3 : z2) + 1e-16f);

    float* op = out + (size_t)dst * 256 + lane * 4;
    float4 bv1 = *(const float4*)(bias + lane * 4);
    float4 bv2 = *(const float4*)(bias + 128 + lane * 4);
    float4 r1 = make_float4(fmaf(acc[0], i1, bv1.x), fmaf(acc[1], i1, bv1.y),
                            fmaf(acc[2], i1, bv1.z), fmaf(acc[3], i1, bv1.w));
    float4 r2 = make_float4(fmaf(acc[4], i2, bv2.x), fmaf(acc[5], i2, bv2.y),
                            fmaf(acc[6], i2, bv2.z), fmaf(acc[7], i2, bv2.w));
    if (addFlag) {
        float4 o1 = *(const float4*)(op);
        float4 o2 = *(const float4*)(op + 128);
        r1.x += o1.x; r1.y += o1.y; r1.z += o1.z; r1.w += o1.w;
        r2.x += o2.x; r2.y += o2.y; r2.z += o2.z; r2.w += o2.w;
    }
    *(float4*)(op) = r1;
    *(float4*)(op + 128) = r2;
}

// ---------------- launcher --------------------------------------------------
extern "C" void kernel_launch(void* const* d_in, const int* in_sizes, int n_in,
                              void* d_out, int out_size)
{
    const float* x  = (const float*)d_in[0];
    const int*   ea = (const int*)d_in[1];
    const int*   eb = (const int*)d_in[2];
    // per-conv weights: W, a_src, a_dst, b
    const float* W0a = (const float*)d_in[3];
    const float* as0a = (const float*)d_in[4];
    const float* ad0a = (const float*)d_in[5];
    const float* b0a = (const float*)d_in[6];
    const float* W0b = (const float*)d_in[7];
    const float* as0b = (const float*)d_in[8];
    const float* ad0b = (const float*)d_in[9];
    const float* b0b = (const float*)d_in[10];
    const float* W1a = (const float*)d_in[11];
    const float* as1a = (const float*)d_in[12];
    const float* ad1a = (const float*)d_in[13];
    const float* b1a = (const float*)d_in[14];
    const float* W1b = (const float*)d_in[15];
    const float* as1b = (const float*)d_in[16];
    const float* ad1b = (const float*)d_in[17];
    const float* b1b = (const float*)d_in[18];
    const float* Wout = (const float*)d_in[19];
    const float* bout = (const float*)d_in[20];
    float* out = (float*)d_out;

    float *lin, *h0, *h1, *ssp, *sdp, *wpad;
    int *rpa, *rpb, *csa, *csb, *deg, *cur, *part;
    cudaGetSymbolAddress((void**)&lin, g_lin);
    cudaGetSymbolAddress((void**)&h0, g_h0);
    cudaGetSymbolAddress((void**)&h1, g_h1);
    cudaGetSymbolAddress((void**)&ssp, g_ss);
    cudaGetSymbolAddress((void**)&sdp, g_sd);
    cudaGetSymbolAddress((void**)&wpad, g_wpad);
    cudaGetSymbolAddress((void**)&rpa, g_rpa);
    cudaGetSymbolAddress((void**)&rpb, g_rpb);
    cudaGetSymbolAddress((void**)&csa, g_csa);
    cudaGetSymbolAddress((void**)&csb, g_csb);
    cudaGetSymbolAddress((void**)&deg, g_deg);
    cudaGetSymbolAddress((void**)&cur, g_cur);
    cudaGetSymbolAddress((void**)&part, g_part);

    const int* srca = ea;
    const int* dsta = ea + EE;
    const int* srcb = eb;
    const int* dstb = eb + EE;

    const int ZB = (NN + 1 + 255) / 256;
    const int EB = (EE + 255) / 256;

    // CSR for edge type a
    zero_int_kernel<<<ZB, 256>>>(deg, NN + 1);
    count_kernel<<<EB, 256>>>(dsta, deg);
    scan_part_kernel<<<NCHUNK, 512>>>(deg, part);
    scan_mid_kernel<<<1, 32>>>(part, NCHUNK);
    scan_final_kernel<<<NCHUNK, 512>>>(deg, part, rpa, cur);
    scatter_kernel<<<EB, 256>>>(srca, dsta, cur, csa);
    // CSR for edge type b
    zero_int_kernel<<<ZB, 256>>>(deg, NN + 1);
    count_kernel<<<EB, 256>>>(dstb, deg);
    scan_part_kernel<<<NCHUNK, 512>>>(deg, part);
    scan_mid_kernel<<<1, 32>>>(part, NCHUNK);
    scan_final_kernel<<<NCHUNK, 512>>>(deg, part, rpb, cur);
    scatter_kernel<<<EB, 256>>>(srcb, dstb, cur, csb);

    pad_wout_kernel<<<256, 256>>>(Wout, wpad);

    dim3 gemmGrid((NN + 127) / 128, 2);
    const int NODE_BLKS = (NN + 7) / 8;

    // layer 0, edge type a
    gemm_kernel<false, false, true><<<gemmGrid, 256>>>(x, W0a, nullptr, lin, NN, 256, 256);
    scores_kernel<<<NODE_BLKS, 256>>>(lin, as0a, ad0a, ssp, sdp);
    aggregate_kernel<<<NODE_BLKS, 256>>>(lin, rpa, csa, ssp, sdp, b0a, h0, 0);
    // layer 0, edge type b (adds into h0)
    gemm_kernel<false, false, true><<<gemmGrid, 256>>>(x, W0b, nullptr, lin, NN, 256, 256);
    scores_kernel<<<NODE_BLKS, 256>>>(lin, as0b, ad0b, ssp, sdp);
    aggregate_kernel<<<NODE_BLKS, 256>>>(lin, rpb, csb, ssp, sdp, b0b, h0, 1);
    // layer 1, edge type a (GEMM applies leaky_relu(0.01) to h0 on load)
    gemm_kernel<true, false, true><<<gemmGrid, 256>>>(h0, W1a, nullptr, lin, NN, 256, 256);
    scores_kernel<<<NODE_BLKS, 256>>>(lin, as1a, ad1a, ssp, sdp);
    aggregate_kernel<<<NODE_BLKS, 256>>>(lin, rpa, csa, ssp, sdp, b1a, h1, 0);
    // layer 1, edge type b
    gemm_kernel<true, false, true><<<gemmGrid, 256>>>(h0, W1b, nullptr, lin, NN, 256, 256);
    scores_kernel<<<NODE_BLKS, 256>>>(lin, as1b, ad1b, ssp, sdp);
    aggregate_kernel<<<NODE_BLKS, 256>>>(lin, rpb, csb, ssp, sdp, b1b, h1, 1);
    // output projection: out = h1 @ Wout + bout  (NC=153, ld 153, scalar store)
    gemm_kernel<false, true, false><<<gemmGrid, 256>>>(h1, wpad, bout, out, NN, 153, 153);
}